// round 14
// baseline (speedup 1.0000x reference)
#include <cuda_runtime.h>
#include <cstdint>

// Shapes fixed by the problem: [B=4, C=32, H=1024, W=1024] fp32 -> [B,H,W] fp32
#define CCH 32
#define HH  1024
#define WW  1024
#define RAD 25    // kernel_radius = W // 40 = 25 (window = 51)
#define RPB 2     // rows per block in kernel A
#define PAD 32    // zero-pad rows above/below each image in scratch (>= RAD+1)
#define HP  (HH + 2 * PAD)
#define NSTG 3    // cp.async pipeline depth in kernel A

// padded scratch: channel-summed + box-w'd intermediate, with zero halo rows
__device__ float g_scratch[4 * HP * WW];

__device__ __forceinline__ float sqrt_approx(float s) {
    float r;
    asm("sqrt.approx.f32 %0, %1;" : "=f"(r) : "f"(s));
    return r;   // sqrt.approx(0) = 0, no NaN guard needed
}

// L2 evict_last access policy (keeps scratch resident for kernel B)
__device__ __forceinline__ unsigned long long evict_last_policy() {
    unsigned long long pol;
    asm("createpolicy.fractional.L2::evict_last.b64 %0, 1.0;" : "=l"(pol));
    return pol;
}

// 128-bit store with L2 evict_last cache hint
__device__ __forceinline__ void st_evict_last4(float* p, float4 v, unsigned long long pol) {
    asm volatile("st.global.L2::cache_hint.v4.f32 [%0], {%1,%2,%3,%4}, %5;"
                 :: "l"(p), "f"(v.x), "f"(v.y), "f"(v.z), "f"(v.w), "l"(pol) : "memory");
}

// 16-byte async global->shared copy (LDGSTS)
__device__ __forceinline__ void cp16(void* s, const void* g) {
    uint32_t sa = (uint32_t)__cvta_generic_to_shared(s);
    asm volatile("cp.async.cg.shared.global [%0], [%1], 16;" :: "r"(sa), "l"(g) : "memory");
}

// ---------------------------------------------------------------------------
// Kernel A: per (b, 2-row tile) — gradient magnitude, channel sum, box-w.
// 3-stage cp.async smem pipeline: channel c's 3 rows (prev/cur0/cur1) were
// issued 3 channel-iterations earlier, so DRAM latency is fully hidden with
// NO register-pipeline pressure. Left neighbors come from smem for free.
// Blocks 0..63 of each image also zero one halo row. evict_last scratch stores.
// ---------------------------------------------------------------------------
__global__ __launch_bounds__(256) void grad_boxw_kernel(const float* __restrict__ x) {
    const int h0   = blockIdx.x * RPB;
    const int b    = blockIdx.y;
    const int tid  = threadIdx.x;
    const int lane = tid & 31;
    const int wid  = tid >> 5;
    const int w0   = tid << 2;

    __shared__ float stg[NSTG][3][WW];   // 36 KB ring: prev / cur0 / cur1
    __shared__ float S[WW + 1];
    __shared__ float wsum[8];

    const unsigned long long pol = evict_last_policy();

    // ---- fused halo zeroing ----
    if (blockIdx.x < 2 * PAD) {
        int row  = blockIdx.x;
        int prow = (row < PAD) ? row : (HH + row);
        st_evict_last4(g_scratch + ((size_t)b * HP + prow) * WW + 4 * tid,
                       make_float4(0.f, 0.f, 0.f, 0.f), pol);
    }

    const float* xb = x + (size_t)b * CCH * HH * WW;
    const bool has_top  = (h0 > 0);
    const bool has_left = (w0 > 0);

    // stage filler: 3 rows of channel c -> stage st (3x 16B cp.async per thread)
    auto fill = [&](int st, int c) {
        const float* base = xb + (size_t)c * HH * WW;
        const float* rp = base + (size_t)(has_top ? h0 - 1 : h0) * WW;  // prev (dummy if top edge)
        const float* r0 = base + (size_t)h0 * WW;
        const float* r1 = r0 + WW;
        cp16(&stg[st][0][4 * tid], rp + 4 * tid);
        cp16(&stg[st][1][4 * tid], r0 + 4 * tid);
        cp16(&stg[st][2][4 * tid], r1 + 4 * tid);
    };

    float a00 = 0.f, a01 = 0.f, a02 = 0.f, a03 = 0.f;
    float a10 = 0.f, a11 = 0.f, a12 = 0.f, a13 = 0.f;

    // ---- prologue: prefill the pipeline ----
    #pragma unroll
    for (int s = 0; s < NSTG; ++s) {
        fill(s, s);
        asm volatile("cp.async.commit_group;" ::: "memory");
    }

    for (int c = 0; c < CCH; ++c) {
        const int st = c % NSTG;

        asm volatile("cp.async.wait_group %0;" :: "n"(NSTG - 1) : "memory");
        __syncthreads();

        // ---- compute channel c from smem ----
        float4 prev = has_top ? *reinterpret_cast<const float4*>(&stg[st][0][w0])
                              : make_float4(0.f, 0.f, 0.f, 0.f);
        float4 c0 = *reinterpret_cast<const float4*>(&stg[st][1][w0]);
        float4 c1 = *reinterpret_cast<const float4*>(&stg[st][2][w0]);
        float  l0 = has_left ? stg[st][1][w0 - 1] : 0.f;
        float  l1 = has_left ? stg[st][2][w0 - 1] : 0.f;

        {
            float dx0 = l0   - c0.x;
            float dx1 = c0.x - c0.y;
            float dx2 = c0.y - c0.z;
            float dx3 = c0.z - c0.w;
            float dy0 = prev.x - c0.x;
            float dy1 = prev.y - c0.y;
            float dy2 = prev.z - c0.z;
            float dy3 = prev.w - c0.w;
            a00 += sqrt_approx(dx0 * dx0 + dy0 * dy0);
            a01 += sqrt_approx(dx1 * dx1 + dy1 * dy1);
            a02 += sqrt_approx(dx2 * dx2 + dy2 * dy2);
            a03 += sqrt_approx(dx3 * dx3 + dy3 * dy3);
        }
        {
            float dx0 = l1   - c1.x;
            float dx1 = c1.x - c1.y;
            float dx2 = c1.y - c1.z;
            float dx3 = c1.z - c1.w;
            float dy0 = c0.x - c1.x;
            float dy1 = c0.y - c1.y;
            float dy2 = c0.z - c1.z;
            float dy3 = c0.w - c1.w;
            a10 += sqrt_approx(dx0 * dx0 + dy0 * dy0);
            a11 += sqrt_approx(dx1 * dx1 + dy1 * dy1);
            a12 += sqrt_approx(dx2 * dx2 + dy2 * dy2);
            a13 += sqrt_approx(dx3 * dx3 + dy3 * dy3);
        }

        __syncthreads();   // all threads done reading stage st

        if (c + NSTG < CCH) fill(st, c + NSTG);
        asm volatile("cp.async.commit_group;" ::: "memory");  // keep group count in lockstep
    }

    // ---- per-row block prefix sum + box-w, 2 rows sequentially ----
    float* gb = g_scratch + (size_t)b * HP * WW + (size_t)PAD * WW;

    #pragma unroll 1
    for (int r = 0; r < RPB; ++r) {
        float v0 = (r == 0) ? a00 : a10;
        float v1 = (r == 0) ? a01 : a11;
        float v2 = (r == 0) ? a02 : a12;
        float v3 = (r == 0) ? a03 : a13;

        float p0 = v0;
        float p1 = p0 + v1;
        float p2 = p1 + v2;
        float p3 = p2 + v3;
        float t  = p3;

        // inclusive warp scan
        float sc = t;
        #pragma unroll
        for (int o = 1; o < 32; o <<= 1) {
            float v = __shfl_up_sync(0xffffffffu, sc, o);
            if (lane >= o) sc += v;
        }
        if (lane == 31) wsum[wid] = sc;
        __syncthreads();
        if (wid == 0) {
            float wv = (lane < 8) ? wsum[lane] : 0.f;
            float ws = wv;
            #pragma unroll
            for (int o = 1; o < 8; o <<= 1) {
                float v = __shfl_up_sync(0xffffffffu, ws, o);
                if (lane >= o) ws += v;
            }
            if (lane < 8) wsum[lane] = ws - wv;
        }
        __syncthreads();

        float bofs = wsum[wid] + (sc - t);
        if (tid == 0) S[0] = 0.f;
        S[w0 + 1] = bofs + p0;
        S[w0 + 2] = bofs + p1;
        S[w0 + 3] = bofs + p2;
        S[w0 + 4] = bofs + p3;
        __syncthreads();

        // vectorized, L2-pinned store of the 4 box-w outputs
        float4 o4;
        {
            int w  = w0;
            int lo = max(0, w - RAD);
            int hi = min(WW - 1, w + RAD);
            o4.x = S[hi + 1] - S[lo];
        }
        {
            int w  = w0 + 1;
            int lo = max(0, w - RAD);
            int hi = min(WW - 1, w + RAD);
            o4.y = S[hi + 1] - S[lo];
        }
        {
            int w  = w0 + 2;
            int lo = max(0, w - RAD);
            int hi = min(WW - 1, w + RAD);
            o4.z = S[hi + 1] - S[lo];
        }
        {
            int w  = w0 + 3;
            int lo = max(0, w - RAD);
            int hi = min(WW - 1, w + RAD);
            o4.w = S[hi + 1] - S[lo];
        }
        st_evict_last4(gb + (size_t)(h0 + r) * WW + w0, o4, pol);
        __syncthreads();
    }
}

// ---------------------------------------------------------------------------
// Kernel B (FROZEN — measured ~10.1-10.4us floor): box filter along h,
// HT=32 @ 256 threads, 8-wide chain split, branch-free via zero halo rows.
// ---------------------------------------------------------------------------
#define HT 32
__global__ __launch_bounds__(256) void boxh_kernel(float* __restrict__ out) {
    const int col = blockIdx.x * 256 + threadIdx.x;  // scalar column
    const int h0  = blockIdx.y * HT;
    const int b   = blockIdx.z;

    const float* gp = g_scratch + ((size_t)b * HP + PAD) * WW + col;  // row 0
    float*       op = out + (size_t)b * HH * WW + col;

    // window init over [h0-RAD, h0+RAD] — in-bounds thanks to halo
    float t0 = 0.f, t1 = 0.f, t2 = 0.f, t3 = 0.f;
    #pragma unroll
    for (int j = 0; j < 48; j += 4) {
        t0 += gp[(size_t)(h0 - RAD + j + 0) * WW];
        t1 += gp[(size_t)(h0 - RAD + j + 1) * WW];
        t2 += gp[(size_t)(h0 - RAD + j + 2) * WW];
        t3 += gp[(size_t)(h0 - RAD + j + 3) * WW];
    }
    t0 += gp[(size_t)(h0 + RAD - 2) * WW];
    t1 += gp[(size_t)(h0 + RAD - 1) * WW];
    t2 += gp[(size_t)(h0 + RAD) * WW];

    float s = (t0 + t1) + (t2 + t3);

    // 8-wide sliding window: one chain advance per 8 output rows
    #pragma unroll
    for (int i = 0; i < HT; i += 8) {
        const int h = h0 + i;
        float A0 = gp[(size_t)(h + RAD + 1) * WW];
        float A1 = gp[(size_t)(h + RAD + 2) * WW];
        float A2 = gp[(size_t)(h + RAD + 3) * WW];
        float A3 = gp[(size_t)(h + RAD + 4) * WW];
        float A4 = gp[(size_t)(h + RAD + 5) * WW];
        float A5 = gp[(size_t)(h + RAD + 6) * WW];
        float A6 = gp[(size_t)(h + RAD + 7) * WW];
        float A7 = gp[(size_t)(h + RAD + 8) * WW];
        float B0 = gp[(size_t)(h - RAD + 0) * WW];
        float B1 = gp[(size_t)(h - RAD + 1) * WW];
        float B2 = gp[(size_t)(h - RAD + 2) * WW];
        float B3 = gp[(size_t)(h - RAD + 3) * WW];
        float B4 = gp[(size_t)(h - RAD + 4) * WW];
        float B5 = gp[(size_t)(h - RAD + 5) * WW];
        float B6 = gp[(size_t)(h - RAD + 6) * WW];
        float B7 = gp[(size_t)(h - RAD + 7) * WW];

        float d0 = A0 - B0;
        float d1 = A1 - B1;
        float d2 = A2 - B2;
        float d3 = A3 - B3;
        float d4 = A4 - B4;
        float d5 = A5 - B5;
        float d6 = A6 - B6;
        float d7 = A7 - B7;

        float d01   = d0 + d1;
        float d23   = d2 + d3;
        float d45   = d4 + d5;
        float d67   = d6 + d7;
        float d0123 = d01 + d23;
        float d4567 = d45 + d67;

        op[(size_t)(h + 0) * WW] = s;
        op[(size_t)(h + 1) * WW] = s + d0;
        op[(size_t)(h + 2) * WW] = s + d01;
        op[(size_t)(h + 3) * WW] = s + (d01 + d2);
        op[(size_t)(h + 4) * WW] = s + d0123;
        op[(size_t)(h + 5) * WW] = s + (d0123 + d4);
        op[(size_t)(h + 6) * WW] = s + (d0123 + d45);
        op[(size_t)(h + 7) * WW] = s + (d0123 + (d45 + d6));
        s += d0123 + d4567;
    }
}

// ---------------------------------------------------------------------------

extern "C" void kernel_launch(void* const* d_in, const int* in_sizes, int n_in,
                              void* d_out, int out_size) {
    const float* x = (const float*)d_in[0];
    float* out = (float*)d_out;

    const int n = in_sizes[0];
    const int B = n / (CCH * HH * WW);   // 4

    dim3 gridA(HH / RPB, B);
    grad_boxw_kernel<<<gridA, 256>>>(x);

    dim3 gridB(WW / 256, HH / HT, B);
    boxh_kernel<<<gridB, 256>>>(out);
}

// round 15
// speedup vs baseline: 1.0163x; 1.0163x over previous
#include <cuda_runtime.h>

// Shapes fixed by the problem: [B=4, C=32, H=1024, W=1024] fp32 -> [B,H,W] fp32
#define CCH 32
#define HH  1024
#define WW  1024
#define RAD 25    // kernel_radius = W // 40 = 25 (window = 51)
#define RPB 2     // rows per block in kernel A
#define PAD 32    // zero-pad rows above/below each image in scratch (>= RAD+1)
#define HP  (HH + 2 * PAD)

// padded scratch: channel-summed + box-w'd intermediate, with zero halo rows
__device__ float g_scratch[4 * HP * WW];

__device__ __forceinline__ float sqrt_approx(float s) {
    float r;
    asm("sqrt.approx.f32 %0, %1;" : "=f"(r) : "f"(s));
    return r;   // sqrt.approx(0) = 0, no NaN guard needed
}

// L2 evict_last access policy (keeps scratch resident for kernel B)
__device__ __forceinline__ unsigned long long evict_last_policy() {
    unsigned long long pol;
    asm("createpolicy.fractional.L2::evict_last.b64 %0, 1.0;" : "=l"(pol));
    return pol;
}

// 128-bit store with L2 evict_last cache hint
__device__ __forceinline__ void st_evict_last4(float* p, float4 v, unsigned long long pol) {
    asm volatile("st.global.L2::cache_hint.v4.f32 [%0], {%1,%2,%3,%4}, %5;"
                 :: "l"(p), "f"(v.x), "f"(v.y), "f"(v.z), "f"(v.w), "l"(pol) : "memory");
}

// ---------------------------------------------------------------------------
// Kernel A: per (b, 2-row tile) — gradient magnitude, channel sum, box-w.
// Main loop: round-13 proven register 1-deep pipeline (86.4us, DRAM-bound).
// Epilogue: FUSED dual-row scan — both rows' prefix sums in one barrier
// sequence (3 syncthreads instead of 8).
// ---------------------------------------------------------------------------
__global__ __launch_bounds__(256, 5) void grad_boxw_kernel(const float* __restrict__ x) {
    const int h0   = blockIdx.x * RPB;
    const int b    = blockIdx.y;
    const int tid  = threadIdx.x;
    const int lane = tid & 31;
    const int wid  = tid >> 5;
    const int w0   = tid << 2;

    const unsigned long long pol = evict_last_policy();

    // ---- fused halo zeroing ----
    if (blockIdx.x < 2 * PAD) {
        int row  = blockIdx.x;
        int prow = (row < PAD) ? row : (HH + row);
        st_evict_last4(g_scratch + ((size_t)b * HP + prow) * WW + 4 * tid,
                       make_float4(0.f, 0.f, 0.f, 0.f), pol);
    }

    const float* xb = x + (size_t)b * CCH * HH * WW;
    const bool has_top  = (h0 > 0);
    const bool has_left = (w0 > 0);

    float a00 = 0.f, a01 = 0.f, a02 = 0.f, a03 = 0.f;
    float a10 = 0.f, a11 = 0.f, a12 = 0.f, a13 = 0.f;

    // ---- prologue: loads for channel 0 ----
    const float* row0 = xb + (size_t)h0 * WW;
    const float* row1 = row0 + WW;
    float4 prev = has_top ? *reinterpret_cast<const float4*>(row0 - WW + w0)
                          : make_float4(0.f, 0.f, 0.f, 0.f);
    float4 c0 = *reinterpret_cast<const float4*>(row0 + w0);
    float4 c1 = *reinterpret_cast<const float4*>(row1 + w0);
    float  l0 = has_left ? row0[w0 - 1] : 0.f;
    float  l1 = has_left ? row1[w0 - 1] : 0.f;

    for (int c = 0; c < CCH; ++c) {
        // ---- prefetch next channel (independent of current compute) ----
        float4 nprev = make_float4(0.f, 0.f, 0.f, 0.f);
        float4 nc0, nc1;
        float  nl0 = 0.f, nl1 = 0.f;
        if (c + 1 < CCH) {
            const float* nrow0 = xb + (size_t)(c + 1) * HH * WW + (size_t)h0 * WW;
            const float* nrow1 = nrow0 + WW;
            if (has_top) nprev = *reinterpret_cast<const float4*>(nrow0 - WW + w0);
            nc0 = *reinterpret_cast<const float4*>(nrow0 + w0);
            nc1 = *reinterpret_cast<const float4*>(nrow1 + w0);
            if (has_left) { nl0 = nrow0[w0 - 1]; nl1 = nrow1[w0 - 1]; }
        } else {
            nc0 = nc1 = make_float4(0.f, 0.f, 0.f, 0.f);
        }

        // ---- compute current channel ----
        {
            float dx0 = l0   - c0.x;
            float dx1 = c0.x - c0.y;
            float dx2 = c0.y - c0.z;
            float dx3 = c0.z - c0.w;
            float dy0 = prev.x - c0.x;
            float dy1 = prev.y - c0.y;
            float dy2 = prev.z - c0.z;
            float dy3 = prev.w - c0.w;
            a00 += sqrt_approx(dx0 * dx0 + dy0 * dy0);
            a01 += sqrt_approx(dx1 * dx1 + dy1 * dy1);
            a02 += sqrt_approx(dx2 * dx2 + dy2 * dy2);
            a03 += sqrt_approx(dx3 * dx3 + dy3 * dy3);
        }
        {
            float dx0 = l1   - c1.x;
            float dx1 = c1.x - c1.y;
            float dx2 = c1.y - c1.z;
            float dx3 = c1.z - c1.w;
            float dy0 = c0.x - c1.x;
            float dy1 = c0.y - c1.y;
            float dy2 = c0.z - c1.z;
            float dy3 = c0.w - c1.w;
            a10 += sqrt_approx(dx0 * dx0 + dy0 * dy0);
            a11 += sqrt_approx(dx1 * dx1 + dy1 * dy1);
            a12 += sqrt_approx(dx2 * dx2 + dy2 * dy2);
            a13 += sqrt_approx(dx3 * dx3 + dy3 * dy3);
        }

        prev = nprev; c0 = nc0; c1 = nc1; l0 = nl0; l1 = nl1;
    }

    // ---- FUSED dual-row block prefix sum + box-w (3 barriers total) ----
    __shared__ float S2[2][WW + 1];
    __shared__ float wsum2[2][8];

    float* gb = g_scratch + (size_t)b * HP * WW + (size_t)PAD * WW;

    // per-thread inclusive prefixes, both rows
    float p00 = a00, p01 = p00 + a01, p02 = p01 + a02, p03 = p02 + a03;
    float p10 = a10, p11 = p10 + a11, p12 = p11 + a12, p13 = p12 + a13;
    float t0 = p03, t1 = p13;

    // two independent warp scans (back-to-back for ILP)
    float sc0 = t0, sc1 = t1;
    #pragma unroll
    for (int o = 1; o < 32; o <<= 1) {
        float v0 = __shfl_up_sync(0xffffffffu, sc0, o);
        float v1 = __shfl_up_sync(0xffffffffu, sc1, o);
        if (lane >= o) { sc0 += v0; sc1 += v1; }
    }
    if (lane == 31) { wsum2[0][wid] = sc0; wsum2[1][wid] = sc1; }
    __syncthreads();                                            // barrier 1

    if (wid == 0) {
        // 16 lanes: lanes 0-7 scan row 0's warp sums, lanes 8-15 row 1's
        int r = lane >> 3;
        int i = lane & 7;
        float wv = (lane < 16) ? wsum2[r][i] : 0.f;
        float ws = wv;
        #pragma unroll
        for (int o = 1; o < 8; o <<= 1) {
            float v = __shfl_up_sync(0xffffffffu, ws, o);
            if ((lane & 7) >= o) ws += v;   // segmented: no carry across lane 8
        }
        if (lane < 16) wsum2[r][i] = ws - wv;  // exclusive warp offsets
    }
    __syncthreads();                                            // barrier 2

    float base0 = wsum2[0][wid] + (sc0 - t0);
    float base1 = wsum2[1][wid] + (sc1 - t1);
    if (tid == 0) { S2[0][0] = 0.f; S2[1][0] = 0.f; }
    S2[0][w0 + 1] = base0 + p00;
    S2[0][w0 + 2] = base0 + p01;
    S2[0][w0 + 3] = base0 + p02;
    S2[0][w0 + 4] = base0 + p03;
    S2[1][w0 + 1] = base1 + p10;
    S2[1][w0 + 2] = base1 + p11;
    S2[1][w0 + 3] = base1 + p12;
    S2[1][w0 + 4] = base1 + p13;
    __syncthreads();                                            // barrier 3

    #pragma unroll
    for (int r = 0; r < RPB; ++r) {
        float4 o4;
        {
            int w  = w0;
            int lo = max(0, w - RAD);
            int hi = min(WW - 1, w + RAD);
            o4.x = S2[r][hi + 1] - S2[r][lo];
        }
        {
            int w  = w0 + 1;
            int lo = max(0, w - RAD);
            int hi = min(WW - 1, w + RAD);
            o4.y = S2[r][hi + 1] - S2[r][lo];
        }
        {
            int w  = w0 + 2;
            int lo = max(0, w - RAD);
            int hi = min(WW - 1, w + RAD);
            o4.z = S2[r][hi + 1] - S2[r][lo];
        }
        {
            int w  = w0 + 3;
            int lo = max(0, w - RAD);
            int hi = min(WW - 1, w + RAD);
            o4.w = S2[r][hi + 1] - S2[r][lo];
        }
        st_evict_last4(gb + (size_t)(h0 + r) * WW + w0, o4, pol);
    }
}

// ---------------------------------------------------------------------------
// Kernel B (FROZEN — measured ~10.1-10.4us floor): box filter along h,
// HT=32 @ 256 threads, 8-wide chain split, branch-free via zero halo rows.
// ---------------------------------------------------------------------------
#define HT 32
__global__ __launch_bounds__(256) void boxh_kernel(float* __restrict__ out) {
    const int col = blockIdx.x * 256 + threadIdx.x;  // scalar column
    const int h0  = blockIdx.y * HT;
    const int b   = blockIdx.z;

    const float* gp = g_scratch + ((size_t)b * HP + PAD) * WW + col;  // row 0
    float*       op = out + (size_t)b * HH * WW + col;

    // window init over [h0-RAD, h0+RAD] — in-bounds thanks to halo
    float t0 = 0.f, t1 = 0.f, t2 = 0.f, t3 = 0.f;
    #pragma unroll
    for (int j = 0; j < 48; j += 4) {
        t0 += gp[(size_t)(h0 - RAD + j + 0) * WW];
        t1 += gp[(size_t)(h0 - RAD + j + 1) * WW];
        t2 += gp[(size_t)(h0 - RAD + j + 2) * WW];
        t3 += gp[(size_t)(h0 - RAD + j + 3) * WW];
    }
    t0 += gp[(size_t)(h0 + RAD - 2) * WW];
    t1 += gp[(size_t)(h0 + RAD - 1) * WW];
    t2 += gp[(size_t)(h0 + RAD) * WW];

    float s = (t0 + t1) + (t2 + t3);

    // 8-wide sliding window: one chain advance per 8 output rows
    #pragma unroll
    for (int i = 0; i < HT; i += 8) {
        const int h = h0 + i;
        float A0 = gp[(size_t)(h + RAD + 1) * WW];
        float A1 = gp[(size_t)(h + RAD + 2) * WW];
        float A2 = gp[(size_t)(h + RAD + 3) * WW];
        float A3 = gp[(size_t)(h + RAD + 4) * WW];
        float A4 = gp[(size_t)(h + RAD + 5) * WW];
        float A5 = gp[(size_t)(h + RAD + 6) * WW];
        float A6 = gp[(size_t)(h + RAD + 7) * WW];
        float A7 = gp[(size_t)(h + RAD + 8) * WW];
        float B0 = gp[(size_t)(h - RAD + 0) * WW];
        float B1 = gp[(size_t)(h - RAD + 1) * WW];
        float B2 = gp[(size_t)(h - RAD + 2) * WW];
        float B3 = gp[(size_t)(h - RAD + 3) * WW];
        float B4 = gp[(size_t)(h - RAD + 4) * WW];
        float B5 = gp[(size_t)(h - RAD + 5) * WW];
        float B6 = gp[(size_t)(h - RAD + 6) * WW];
        float B7 = gp[(size_t)(h - RAD + 7) * WW];

        float d0 = A0 - B0;
        float d1 = A1 - B1;
        float d2 = A2 - B2;
        float d3 = A3 - B3;
        float d4 = A4 - B4;
        float d5 = A5 - B5;
        float d6 = A6 - B6;
        float d7 = A7 - B7;

        float d01   = d0 + d1;
        float d23   = d2 + d3;
        float d45   = d4 + d5;
        float d67   = d6 + d7;
        float d0123 = d01 + d23;
        float d4567 = d45 + d67;

        op[(size_t)(h + 0) * WW] = s;
        op[(size_t)(h + 1) * WW] = s + d0;
        op[(size_t)(h + 2) * WW] = s + d01;
        op[(size_t)(h + 3) * WW] = s + (d01 + d2);
        op[(size_t)(h + 4) * WW] = s + d0123;
        op[(size_t)(h + 5) * WW] = s + (d0123 + d4);
        op[(size_t)(h + 6) * WW] = s + (d0123 + d45);
        op[(size_t)(h + 7) * WW] = s + (d0123 + (d45 + d6));
        s += d0123 + d4567;
    }
}

// ---------------------------------------------------------------------------

extern "C" void kernel_launch(void* const* d_in, const int* in_sizes, int n_in,
                              void* d_out, int out_size) {
    const float* x = (const float*)d_in[0];
    float* out = (float*)d_out;

    const int n = in_sizes[0];
    const int B = n / (CCH * HH * WW);   // 4

    dim3 gridA(HH / RPB, B);
    grad_boxw_kernel<<<gridA, 256>>>(x);

    dim3 gridB(WW / 256, HH / HT, B);
    boxh_kernel<<<gridB, 256>>>(out);
}